// round 1
// baseline (speedup 1.0000x reference)
#include <cuda_runtime.h>
#include <math_constants.h>

namespace {

constexpr int Cc = 192;
constexpr int Hh = 128;
constexpr int Ww = 128;
constexpr int ROWS_PER_WARP = 32;
constexpr int THREADS = 128;   // 4 warps * 32 rows = 128 rows = full plane

__device__ __forceinline__ float fast_sigmoid(float t) {
    // 1 / (1 + exp(-t)); __expf -> FMUL + MUFU.EX2, division -> MUFU.RCP
    return __fdividef(1.0f, 1.0f + __expf(-t));
}

// relax 4 output pixels against one input row (v with halo L/R) and one kernel row
__device__ __forceinline__ void relax(float4& acc, const float4& t,
                                      float L, const float4& v, float R,
                                      float kl, float kc, float kr) {
    acc.x = fmaxf(acc.x, fmaf(t.x, kl, L));
    acc.x = fmaxf(acc.x, fmaf(t.x, kc, v.x));
    acc.x = fmaxf(acc.x, fmaf(t.x, kr, v.y));

    acc.y = fmaxf(acc.y, fmaf(t.y, kl, v.x));
    acc.y = fmaxf(acc.y, fmaf(t.y, kc, v.y));
    acc.y = fmaxf(acc.y, fmaf(t.y, kr, v.z));

    acc.z = fmaxf(acc.z, fmaf(t.z, kl, v.y));
    acc.z = fmaxf(acc.z, fmaf(t.z, kc, v.z));
    acc.z = fmaxf(acc.z, fmaf(t.z, kr, v.w));

    acc.w = fmaxf(acc.w, fmaf(t.w, kl, v.z));
    acc.w = fmaxf(acc.w, fmaf(t.w, kc, v.w));
    acc.w = fmaxf(acc.w, fmaf(t.w, kr, R));
}

__global__ void __launch_bounds__(THREADS, 8)
dynmorph_kernel(const float* __restrict__ x,
                const float* __restrict__ kern,
                const float* __restrict__ gw,
                const float* __restrict__ gb,
                float* __restrict__ out) {
    const int plane = blockIdx.x;            // b*C + c
    const int c     = plane % Cc;
    const int warp  = threadIdx.x >> 5;
    const int lane  = threadIdx.x & 31;

    const float* __restrict__ xp = x   + (size_t)plane * (Hh * Ww);
    float*       __restrict__ op = out + (size_t)plane * (Hh * Ww);

    float k0 = __ldg(&kern[c * 9 + 0]);
    float k1 = __ldg(&kern[c * 9 + 1]);
    float k2 = __ldg(&kern[c * 9 + 2]);
    float k3 = __ldg(&kern[c * 9 + 3]);
    float k4 = __ldg(&kern[c * 9 + 4]);
    float k5 = __ldg(&kern[c * 9 + 5]);
    float k6 = __ldg(&kern[c * 9 + 6]);
    float k7 = __ldg(&kern[c * 9 + 7]);
    float k8 = __ldg(&kern[c * 9 + 8]);
    const float gwc = __ldg(&gw[c]);
    const float gbc = __ldg(&gb[c]);

    const int h0  = warp * ROWS_PER_WARP;
    const int col = lane * 4;

    // rolling 3-row window in registers (float4 per lane = one full row per warp)
    float4 rm, r0, rp;
    float Lm, Rm, L0, R0, Lp, Rp;

    // row h0-1 (zero pad at top of plane)
    if (h0 == 0) {
        rm = make_float4(0.f, 0.f, 0.f, 0.f);
    } else {
        rm = *reinterpret_cast<const float4*>(xp + (size_t)(h0 - 1) * Ww + col);
    }
    {
        float l = __shfl_up_sync(0xffffffffu, rm.w, 1);
        float r = __shfl_down_sync(0xffffffffu, rm.x, 1);
        Lm = (lane == 0) ? 0.f : l;
        Rm = (lane == 31) ? 0.f : r;
    }

    // row h0
    r0 = *reinterpret_cast<const float4*>(xp + (size_t)h0 * Ww + col);
    {
        float l = __shfl_up_sync(0xffffffffu, r0.w, 1);
        float r = __shfl_down_sync(0xffffffffu, r0.x, 1);
        L0 = (lane == 0) ? 0.f : l;
        R0 = (lane == 31) ? 0.f : r;
    }

#pragma unroll 4
    for (int rr = 0; rr < ROWS_PER_WARP; rr++) {
        const int h = h0 + rr;

        // load row h+1 (zero pad at bottom of plane)
        if (h + 1 < Hh) {
            rp = *reinterpret_cast<const float4*>(xp + (size_t)(h + 1) * Ww + col);
        } else {
            rp = make_float4(0.f, 0.f, 0.f, 0.f);
        }
        {
            float l = __shfl_up_sync(0xffffffffu, rp.w, 1);
            float r = __shfl_down_sync(0xffffffffu, rp.x, 1);
            Lp = (lane == 0) ? 0.f : l;
            Rp = (lane == 31) ? 0.f : r;
        }

        // gate from center row
        float4 t;
        t.x = fast_sigmoid(fmaf(r0.x, gwc, gbc));
        t.y = fast_sigmoid(fmaf(r0.y, gwc, gbc));
        t.z = fast_sigmoid(fmaf(r0.z, gwc, gbc));
        t.w = fast_sigmoid(fmaf(r0.w, gwc, gbc));

        float4 acc = make_float4(-CUDART_INF_F, -CUDART_INF_F,
                                 -CUDART_INF_F, -CUDART_INF_F);
        relax(acc, t, Lm, rm, Rm, k0, k1, k2);   // row h-1 -> kernel row 0
        relax(acc, t, L0, r0, R0, k3, k4, k5);   // row h   -> kernel row 1
        relax(acc, t, Lp, rp, Rp, k6, k7, k8);   // row h+1 -> kernel row 2

        *reinterpret_cast<float4*>(op + (size_t)h * Ww + col) = acc;

        // roll window down
        rm = r0; Lm = L0; Rm = R0;
        r0 = rp; L0 = Lp; R0 = Rp;
    }
}

}  // namespace

extern "C" void kernel_launch(void* const* d_in, const int* in_sizes, int n_in,
                              void* d_out, int out_size) {
    const float* x    = (const float*)d_in[0];
    const float* kern = (const float*)d_in[1];
    const float* gw   = (const float*)d_in[2];
    const float* gb   = (const float*)d_in[3];
    float* out        = (float*)d_out;

    const int planes = in_sizes[0] / (Hh * Ww);  // B * C = 1536
    dynmorph_kernel<<<planes, THREADS>>>(x, kern, gw, gb, out);
}

// round 2
// speedup vs baseline: 1.0572x; 1.0572x over previous
#include <cuda_runtime.h>

namespace {

constexpr int Cc = 192;
constexpr int Hh = 128;
constexpr int Ww = 128;
constexpr int ROWS_PER_WARP = 16;
constexpr int WARPS = 4;
constexpr int THREADS = WARPS * 32;
constexpr int ROWS_PER_BLOCK = WARPS * ROWS_PER_WARP;   // 64 = half plane
constexpr int STRIPS_PER_PLANE = Hh / ROWS_PER_BLOCK;   // 2

__device__ __forceinline__ float fast_sigmoid(float t) {
    return __fdividef(1.0f, 1.0f + __expf(-t));
}

// acc = max(acc, patch + t*k) over one input row (with halo L/R), one kernel row
__device__ __forceinline__ void relax(float4& acc, const float4& t,
                                      float L, const float4& v, float R,
                                      float kl, float kc, float kr) {
    acc.x = fmaxf(acc.x, fmaf(t.x, kl, L));
    acc.x = fmaxf(acc.x, fmaf(t.x, kc, v.x));
    acc.x = fmaxf(acc.x, fmaf(t.x, kr, v.y));

    acc.y = fmaxf(acc.y, fmaf(t.y, kl, v.x));
    acc.y = fmaxf(acc.y, fmaf(t.y, kc, v.y));
    acc.y = fmaxf(acc.y, fmaf(t.y, kr, v.z));

    acc.z = fmaxf(acc.z, fmaf(t.z, kl, v.y));
    acc.z = fmaxf(acc.z, fmaf(t.z, kc, v.z));
    acc.z = fmaxf(acc.z, fmaf(t.z, kr, v.w));

    acc.w = fmaxf(acc.w, fmaf(t.w, kl, v.z));
    acc.w = fmaxf(acc.w, fmaf(t.w, kc, v.w));
    acc.w = fmaxf(acc.w, fmaf(t.w, kr, R));
}

// same but initializes acc (saves the -inf seed + 4 extra FMNMX)
__device__ __forceinline__ void relax_init(float4& acc, const float4& t,
                                           float L, const float4& v, float R,
                                           float kl, float kc, float kr) {
    acc.x = fmaf(t.x, kc, v.x);
    acc.y = fmaf(t.y, kc, v.y);
    acc.z = fmaf(t.z, kc, v.z);
    acc.w = fmaf(t.w, kc, v.w);

    acc.x = fmaxf(acc.x, fmaf(t.x, kl, L));
    acc.x = fmaxf(acc.x, fmaf(t.x, kr, v.y));

    acc.y = fmaxf(acc.y, fmaf(t.y, kl, v.x));
    acc.y = fmaxf(acc.y, fmaf(t.y, kr, v.z));

    acc.z = fmaxf(acc.z, fmaf(t.z, kl, v.y));
    acc.z = fmaxf(acc.z, fmaf(t.z, kr, v.w));

    acc.w = fmaxf(acc.w, fmaf(t.w, kl, v.z));
    acc.w = fmaxf(acc.w, fmaf(t.w, kr, R));
}

__global__ void __launch_bounds__(THREADS, 11)
dynmorph_kernel(const float* __restrict__ x,
                const float* __restrict__ kern,
                const float* __restrict__ gw,
                const float* __restrict__ gb,
                float* __restrict__ out) {
    const int strip = blockIdx.x;                   // plane * 2 + half
    const int plane = strip / STRIPS_PER_PLANE;
    const int half  = strip % STRIPS_PER_PLANE;
    const int c     = plane % Cc;
    const int warp  = threadIdx.x >> 5;
    const int lane  = threadIdx.x & 31;

    const float* __restrict__ xp = x   + (size_t)plane * (Hh * Ww);
    float*       __restrict__ op = out + (size_t)plane * (Hh * Ww);

    const float k0 = __ldg(&kern[c * 9 + 0]);
    const float k1 = __ldg(&kern[c * 9 + 1]);
    const float k2 = __ldg(&kern[c * 9 + 2]);
    const float k3 = __ldg(&kern[c * 9 + 3]);
    const float k4 = __ldg(&kern[c * 9 + 4]);
    const float k5 = __ldg(&kern[c * 9 + 5]);
    const float k6 = __ldg(&kern[c * 9 + 6]);
    const float k7 = __ldg(&kern[c * 9 + 7]);
    const float k8 = __ldg(&kern[c * 9 + 8]);
    const float gwc = __ldg(&gw[c]);
    const float gbc = __ldg(&gb[c]);

    const int h0  = half * ROWS_PER_BLOCK + warp * ROWS_PER_WARP;
    const int col = lane * 4;

    // rolling 3-row window in registers (float4 per lane = full row per warp)
    float4 rm, r0, rp;
    float Lm, Rm, L0, R0, Lp, Rp;

    // row h0-1 (zero pad at top of plane)
    if (h0 == 0) {
        rm = make_float4(0.f, 0.f, 0.f, 0.f);
    } else {
        rm = *reinterpret_cast<const float4*>(xp + (size_t)(h0 - 1) * Ww + col);
    }
    {
        float l = __shfl_up_sync(0xffffffffu, rm.w, 1);
        float r = __shfl_down_sync(0xffffffffu, rm.x, 1);
        Lm = (lane == 0) ? 0.f : l;
        Rm = (lane == 31) ? 0.f : r;
    }

    // row h0
    r0 = *reinterpret_cast<const float4*>(xp + (size_t)h0 * Ww + col);
    {
        float l = __shfl_up_sync(0xffffffffu, r0.w, 1);
        float r = __shfl_down_sync(0xffffffffu, r0.x, 1);
        L0 = (lane == 0) ? 0.f : l;
        R0 = (lane == 31) ? 0.f : r;
    }

#pragma unroll 4
    for (int rr = 0; rr < ROWS_PER_WARP; rr++) {
        const int h = h0 + rr;

        // load row h+1 (zero pad at bottom of plane)
        if (h + 1 < Hh) {
            rp = *reinterpret_cast<const float4*>(xp + (size_t)(h + 1) * Ww + col);
        } else {
            rp = make_float4(0.f, 0.f, 0.f, 0.f);
        }
        {
            float l = __shfl_up_sync(0xffffffffu, rp.w, 1);
            float r = __shfl_down_sync(0xffffffffu, rp.x, 1);
            Lp = (lane == 0) ? 0.f : l;
            Rp = (lane == 31) ? 0.f : r;
        }

        // gate from center row
        float4 t;
        t.x = fast_sigmoid(fmaf(r0.x, gwc, gbc));
        t.y = fast_sigmoid(fmaf(r0.y, gwc, gbc));
        t.z = fast_sigmoid(fmaf(r0.z, gwc, gbc));
        t.w = fast_sigmoid(fmaf(r0.w, gwc, gbc));

        float4 acc;
        relax_init(acc, t, Lm, rm, Rm, k0, k1, k2);  // row h-1 -> kernel row 0
        relax(acc, t, L0, r0, R0, k3, k4, k5);       // row h   -> kernel row 1
        relax(acc, t, Lp, rp, Rp, k6, k7, k8);       // row h+1 -> kernel row 2

        *reinterpret_cast<float4*>(op + (size_t)h * Ww + col) = acc;

        // roll window down
        rm = r0; Lm = L0; Rm = R0;
        r0 = rp; L0 = Lp; R0 = Rp;
    }
}

}  // namespace

extern "C" void kernel_launch(void* const* d_in, const int* in_sizes, int n_in,
                              void* d_out, int out_size) {
    const float* x    = (const float*)d_in[0];
    const float* kern = (const float*)d_in[1];
    const float* gw   = (const float*)d_in[2];
    const float* gb   = (const float*)d_in[3];
    float* out        = (float*)d_out;

    const int planes = in_sizes[0] / (Hh * Ww);  // B * C = 1536
    dynmorph_kernel<<<planes * STRIPS_PER_PLANE, THREADS>>>(x, kern, gw, gb, out);
}